// round 8
// baseline (speedup 1.0000x reference)
#include <cuda_runtime.h>
#include <cuda_bf16.h>
#include <cstdint>

// NeuralODE fused RK4, bf16 mma.sync m16n8k16, M=32 rows/warp (2 m-tiles share
// every B-fragment load -> half the crossbar bytes per row). RK4 state (y0, rk4)
// lives in conflict-free per-thread SMEM; MMA fragments stay in registers.
// Per CTA: 256 rows, 8 warps x 32 rows, whole 64-step RK4, zero syncs in loop.

#define D_IN      64
#define HID       256
#define NTHREADS  256
#define BLK_ROWS  256
#define NSTEPS    64

// SMEM (bytes)
#define W1F_OFF   0        // u32[8192]  (32KB)
#define W2F_OFF   32768    // u32[8192]  (32KB)
#define B1_OFF    65536    // float[256]
#define B2_OFF    66560    // float[64]
#define ST_OFF    66816    // state: 8 warps x 4224 floats (y0 2112 | rk4 2112)
#define WST_FLOATS 4224
#define SMEM_BYTES (66816 + 8 * WST_FLOATS * 4)   // 201984

__device__ __forceinline__ uint32_t pack_bf16(float lo, float hi) {
    uint32_t r;
    asm("cvt.rn.bf16x2.f32 %0, %1, %2;" : "=r"(r) : "f"(hi), "f"(lo));
    return r;
}

__device__ __forceinline__ void mma_bf16(float c[4],
                                         uint32_t a0, uint32_t a1, uint32_t a2, uint32_t a3,
                                         uint32_t b0, uint32_t b1) {
    asm volatile(
        "mma.sync.aligned.m16n8k16.row.col.f32.bf16.bf16.f32 "
        "{%0,%1,%2,%3}, {%4,%5,%6,%7}, {%8,%9}, {%0,%1,%2,%3};\n"
        : "+f"(c[0]), "+f"(c[1]), "+f"(c[2]), "+f"(c[3])
        : "r"(a0), "r"(a1), "r"(a2), "r"(a3), "r"(b0), "r"(b1));
}

__device__ __forceinline__ float elu_f(float v) {
    float e = __expf(v) - 1.0f;
    return v > 0.0f ? v : e;
}

__global__ void __launch_bounds__(NTHREADS, 1)
node_rk4_m32_kernel(const float* __restrict__ x,
                    const float* __restrict__ tptr,
                    const float* __restrict__ W1,   // [256,64] row-major
                    const float* __restrict__ b1,   // [256]
                    const float* __restrict__ W2,   // [64,256] row-major
                    const float* __restrict__ b2,   // [64]
                    float* __restrict__ out) {
    extern __shared__ char smem_c[];
    uint32_t* W1f = (uint32_t*)(smem_c + W1F_OFF);
    uint32_t* W2f = (uint32_t*)(smem_c + W2F_OFF);
    float*    b1s = (float*)(smem_c + B1_OFF);
    float*    b2s = (float*)(smem_c + B2_OFF);

    const int tid  = threadIdx.x;
    const int lane = tid & 31;
    const int warp = tid >> 5;
    const int g    = lane >> 2;
    const int tq   = lane & 3;

    // per-thread state: y0[64] then rk4[64], stride 66 words (conflict-free LDS.64)
    float* stp = (float*)(smem_c + ST_OFF) + warp * WST_FLOATS + lane * 66;
    float* rkp = stp + 2112;

    // ---- W1 B-fragments: tile = nt*4 + kt (nt 0..31, kt 0..3); B1[k][n] = W1[n][k]
    for (int i = tid; i < 8192; i += NTHREADS) {
        int j = i & 1, ln = (i >> 1) & 31, tile = i >> 6;
        int nt = tile >> 2, kt = tile & 3;
        int n = nt * 8 + (ln >> 2);
        int k = kt * 16 + 2 * (ln & 3) + (j ? 8 : 0);
        const float2 w = *(const float2*)(W1 + n * D_IN + k);
        W1f[i] = pack_bf16(w.x, w.y);
    }
    // ---- W2 B-fragments: tile = kt2*8 + nt2; B2[k][n] = W2[n][k]
    for (int i = tid; i < 8192; i += NTHREADS) {
        int j = i & 1, ln = (i >> 1) & 31, tile = i >> 6;
        int kt2 = tile >> 3, nt2 = tile & 7;
        int n = nt2 * 8 + (ln >> 2);
        int k = kt2 * 16 + 2 * (ln & 3) + (j ? 8 : 0);
        const float2 w = *(const float2*)(W2 + n * HID + k);
        W2f[i] = pack_bf16(w.x, w.y);
    }
    for (int i = tid; i < HID; i += NTHREADS) b1s[i] = b1[i];
    for (int i = tid; i < D_IN; i += NTHREADS) b2s[i] = b2[i];

    const float t0 = tptr[0];
    const float dt = t0 * 0.015625f;
    const float half_dt = 0.5f * dt;
    const float dt6 = dt * (1.0f / 6.0f);

    // ---- load x: two m16 tiles per warp; y0 -> SMEM, pack A1 frags ----
    const int rbase = blockIdx.x * BLK_ROWS + warp * 32;
    uint32_t a1f[32];   // [mt*16 + kt*4 + r]
#pragma unroll
    for (int mt = 0; mt < 2; ++mt) {
        const float* xr0 = x + (size_t)(rbase + mt * 16 + g) * D_IN + 2 * tq;
        const float* xr1 = x + (size_t)(rbase + mt * 16 + g + 8) * D_IN + 2 * tq;
#pragma unroll
        for (int nt = 0; nt < 8; ++nt) {
            float2 u = *(const float2*)(xr0 + nt * 8);
            float2 v = *(const float2*)(xr1 + nt * 8);
            int eb = mt * 32 + nt * 4;
            *(float2*)(stp + eb)     = u;
            *(float2*)(stp + eb + 2) = v;
            int kt = nt >> 1, r0 = (nt & 1) * 2;
            a1f[mt * 16 + kt * 4 + r0]     = pack_bf16(u.x, u.y);
            a1f[mt * 16 + kt * 4 + r0 + 1] = pack_bf16(v.x, v.y);
        }
    }
    __syncthreads();

#pragma unroll 1
    for (int e = 0; e < NSTEPS * 4; ++e) {
        const int s = e & 3;

        float kacc[2][8][4];
#pragma unroll
        for (int mt = 0; mt < 2; ++mt)
#pragma unroll
            for (int nt = 0; nt < 8; ++nt)
#pragma unroll
                for (int j = 0; j < 4; ++j) kacc[mt][nt][j] = 0.0f;

#pragma unroll 2
        for (int nc = 0; nc < 8; ++nc) {
            // ---- GEMM1 chunk: 4 ntiles (32 hidden cols), K=64, both m-tiles ----
            float c1[2][4][4];
#pragma unroll
            for (int mt = 0; mt < 2; ++mt)
#pragma unroll
                for (int nt = 0; nt < 4; ++nt)
#pragma unroll
                    for (int j = 0; j < 4; ++j) c1[mt][nt][j] = 0.0f;

#pragma unroll
            for (int kt = 0; kt < 4; ++kt) {
#pragma unroll
                for (int nt = 0; nt < 4; ++nt) {
                    const uint2 b = *(const uint2*)(W1f + (((nc * 4 + nt) * 4 + kt) * 64 + lane * 2));
                    mma_bf16(c1[0][nt], a1f[kt * 4], a1f[kt * 4 + 1], a1f[kt * 4 + 2], a1f[kt * 4 + 3], b.x, b.y);
                    mma_bf16(c1[1][nt], a1f[16 + kt * 4], a1f[16 + kt * 4 + 1], a1f[16 + kt * 4 + 2], a1f[16 + kt * 4 + 3], b.x, b.y);
                }
            }

            // ---- bias + ELU + pack: C-frags -> GEMM2 A-frags, both m-tiles ----
            uint32_t hf[2][2][4];
#pragma unroll
            for (int nt = 0; nt < 4; ++nt) {
                const float2 bb = *(const float2*)(b1s + (nc * 32 + nt * 8 + 2 * tq));
#pragma unroll
                for (int mt = 0; mt < 2; ++mt) {
                    float v00 = elu_f(c1[mt][nt][0] + bb.x);
                    float v01 = elu_f(c1[mt][nt][1] + bb.y);
                    float v10 = elu_f(c1[mt][nt][2] + bb.x);
                    float v11 = elu_f(c1[mt][nt][3] + bb.y);
                    hf[mt][nt >> 1][(nt & 1) * 2 + 0] = pack_bf16(v00, v01);
                    hf[mt][nt >> 1][(nt & 1) * 2 + 1] = pack_bf16(v10, v11);
                }
            }

            // ---- GEMM2 partial: 2 ktiles of 16, both m-tiles share B ----
#pragma unroll
            for (int ktl = 0; ktl < 2; ++ktl) {
#pragma unroll
                for (int nt2 = 0; nt2 < 8; ++nt2) {
                    const uint2 b = *(const uint2*)(W2f + (((nc * 2 + ktl) * 8 + nt2) * 64 + lane * 2));
                    mma_bf16(kacc[0][nt2], hf[0][ktl][0], hf[0][ktl][1], hf[0][ktl][2], hf[0][ktl][3], b.x, b.y);
                    mma_bf16(kacc[1][nt2], hf[1][ktl][0], hf[1][ktl][1], hf[1][ktl][2], hf[1][ktl][3], b.x, b.y);
                }
            }
        } // nc

        // ---- epilogue: k = kacc + b2; RK4 state in SMEM; repack A1 frags ----
        const float wk = (s == 1 || s == 2) ? 2.0f : 1.0f;
        const float cn = (s == 2) ? dt : half_dt;
#pragma unroll
        for (int mt = 0; mt < 2; ++mt) {
#pragma unroll
            for (int nt = 0; nt < 8; ++nt) {
                const int eb = mt * 32 + nt * 4;
                const float2 bb = *(const float2*)(b2s + (nt * 8 + 2 * tq));
                float k0 = kacc[mt][nt][0] + bb.x;
                float k1 = kacc[mt][nt][1] + bb.y;
                float k2 = kacc[mt][nt][2] + bb.x;
                float k3 = kacc[mt][nt][3] + bb.y;

                float2 r01, r23;
                if (s == 0) {
                    r01 = make_float2(k0, k1);
                    r23 = make_float2(k2, k3);
                } else {
                    r01 = *(const float2*)(rkp + eb);
                    r23 = *(const float2*)(rkp + eb + 2);
                    r01.x += wk * k0; r01.y += wk * k1;
                    r23.x += wk * k2; r23.y += wk * k3;
                }
                *(float2*)(rkp + eb)     = r01;
                *(float2*)(rkp + eb + 2) = r23;

                float2 y01 = *(const float2*)(stp + eb);
                float2 y23 = *(const float2*)(stp + eb + 2);
                float yn0, yn1, yn2, yn3;
                if (s < 3) {
                    yn0 = y01.x + cn * k0; yn1 = y01.y + cn * k1;
                    yn2 = y23.x + cn * k2; yn3 = y23.y + cn * k3;
                } else {
                    yn0 = y01.x + dt6 * r01.x; yn1 = y01.y + dt6 * r01.y;
                    yn2 = y23.x + dt6 * r23.x; yn3 = y23.y + dt6 * r23.y;
                    *(float2*)(stp + eb)     = make_float2(yn0, yn1);
                    *(float2*)(stp + eb + 2) = make_float2(yn2, yn3);
                }
                int kt = nt >> 1, r0 = (nt & 1) * 2;
                a1f[mt * 16 + kt * 4 + r0]     = pack_bf16(yn0, yn1);
                a1f[mt * 16 + kt * 4 + r0 + 1] = pack_bf16(yn2, yn3);
            }
        }
    } // eval loop

    // ---- write final y0 ----
#pragma unroll
    for (int mt = 0; mt < 2; ++mt) {
        float* or0 = out + (size_t)(rbase + mt * 16 + g) * D_IN + 2 * tq;
        float* or1 = out + (size_t)(rbase + mt * 16 + g + 8) * D_IN + 2 * tq;
#pragma unroll
        for (int nt = 0; nt < 8; ++nt) {
            int eb = mt * 32 + nt * 4;
            *(float2*)(or0 + nt * 8) = *(const float2*)(stp + eb);
            *(float2*)(or1 + nt * 8) = *(const float2*)(stp + eb + 2);
        }
    }
}

extern "C" void kernel_launch(void* const* d_in, const int* in_sizes, int n_in,
                              void* d_out, int out_size) {
    const float* x  = (const float*)d_in[0];
    const float* t  = (const float*)d_in[1];
    const float* W1 = (const float*)d_in[2];
    const float* b1 = (const float*)d_in[3];
    const float* W2 = (const float*)d_in[4];
    const float* b2 = (const float*)d_in[5];
    float* out = (float*)d_out;

    int n_rows = in_sizes[0] / D_IN;      // 262144
    int grid = n_rows / BLK_ROWS;         // 1024

    cudaFuncSetAttribute(node_rk4_m32_kernel,
                         cudaFuncAttributeMaxDynamicSharedMemorySize, SMEM_BYTES);
    node_rk4_m32_kernel<<<grid, NTHREADS, SMEM_BYTES>>>(x, t, W1, b1, W2, b2, out);
}